// round 1
// baseline (speedup 1.0000x reference)
#include <cuda_runtime.h>
#include <cstdint>

#define NART  50000
#define NCOMM 50000
#define FIN   768
#define PROJ  1024
#define HID   256
#define NOUT  128

// ---------------- scratch (device globals; no allocation allowed) ----------
__device__ float g_Wa1[FIN * HID];   // W1 @ Wl1
__device__ float g_Wa2[FIN * HID];   // W1 @ Wl2
__device__ float g_Wc1[FIN * HID];   // W2 @ Wr1
__device__ float g_ba1[HID];         // b1 @ Wl1
__device__ float g_ba2[HID];         // b1 @ Wl2
__device__ float g_bc1[HID];         // b2 @ Wr1
__device__ float g_A1[NART * HID];   // article_x @ Wa1 + ba1   (conv1 msg path)
__device__ float g_A2[NART * HID];   // article_x @ Wa2 + ba2   (conv2 msg path)
__device__ float g_C1[NCOMM * HID];  // community_x @ Wc1 + bc1 (conv1 root path)
__device__ float g_R3[NCOMM * HID];  // community_x @ Wr3       (conv3 root path)
__device__ float g_AGG[NCOMM * HID];
__device__ float g_CNT[NCOMM];
__device__ float g_H1[NCOMM * HID];  // also reused for h3
__device__ float g_H2[NCOMM * HID];
__device__ float g_T[NCOMM * HID];   // h1@Wr2, then h2@Wl3

// ---------------- SGEMM: C[M,N] = A[M,K] @ B[K,N] (+bias) ------------------
// 128x128 block tile, BK=8, 256 threads, 8x8 per-thread microtile.
// Requires: N % 128 == 0 (grid.x = N/128), K % 8 == 0. M guarded.
__global__ void __launch_bounds__(256) sgemm128(
    const float* __restrict__ A, const float* __restrict__ B,
    const float* __restrict__ bias, float* __restrict__ C,
    int M, int N, int K, int doRelu)
{
    __shared__ float As[8][132];   // +4 pad kills STS bank conflicts
    __shared__ float Bs[8][128];
    const int tid = threadIdx.x;
    const int bm = blockIdx.y * 128;
    const int bn = blockIdx.x * 128;
    const int tx = tid & 15;       // 16 col groups
    const int ty = tid >> 4;       // 16 row groups

    float acc[8][8];
#pragma unroll
    for (int i = 0; i < 8; ++i)
#pragma unroll
        for (int j = 0; j < 8; ++j) acc[i][j] = 0.f;

    const int aRow = tid >> 1;          // 0..127
    const int aCol = (tid & 1) * 4;     // 0 or 4
    const int bRow = tid >> 5;          // 0..7
    const int bCol = (tid & 31) * 4;    // 0..124
    const int gARow = bm + aRow;
    const bool aOk = (gARow < M);
    const float* aPtr = A + (size_t)gARow * K + aCol;

    for (int k0 = 0; k0 < K; k0 += 8) {
        float4 av = make_float4(0.f, 0.f, 0.f, 0.f);
        if (aOk) av = *(const float4*)(aPtr + k0);
        As[aCol + 0][aRow] = av.x;
        As[aCol + 1][aRow] = av.y;
        As[aCol + 2][aRow] = av.z;
        As[aCol + 3][aRow] = av.w;
        float4 bv = *(const float4*)(B + (size_t)(k0 + bRow) * N + bn + bCol);
        *(float4*)(&Bs[bRow][bCol]) = bv;
        __syncthreads();
#pragma unroll
        for (int kk = 0; kk < 8; ++kk) {
            float ar[8], br[8];
            float4 a0 = *(const float4*)(&As[kk][ty * 8]);
            float4 a1 = *(const float4*)(&As[kk][ty * 8 + 4]);
            float4 b0 = *(const float4*)(&Bs[kk][tx * 8]);
            float4 b1 = *(const float4*)(&Bs[kk][tx * 8 + 4]);
            ar[0]=a0.x; ar[1]=a0.y; ar[2]=a0.z; ar[3]=a0.w;
            ar[4]=a1.x; ar[5]=a1.y; ar[6]=a1.z; ar[7]=a1.w;
            br[0]=b0.x; br[1]=b0.y; br[2]=b0.z; br[3]=b0.w;
            br[4]=b1.x; br[5]=b1.y; br[6]=b1.z; br[7]=b1.w;
#pragma unroll
            for (int i = 0; i < 8; ++i)
#pragma unroll
                for (int j = 0; j < 8; ++j)
                    acc[i][j] = fmaf(ar[i], br[j], acc[i][j]);
        }
        __syncthreads();
    }

#pragma unroll
    for (int i = 0; i < 8; ++i) {
        int row = bm + ty * 8 + i;
        if (row >= M) continue;
#pragma unroll
        for (int j = 0; j < 8; j += 4) {
            int col = bn + tx * 8 + j;
            float4 v;
            v.x = acc[i][j + 0]; v.y = acc[i][j + 1];
            v.z = acc[i][j + 2]; v.w = acc[i][j + 3];
            if (bias) {
                v.x += bias[col + 0]; v.y += bias[col + 1];
                v.z += bias[col + 2]; v.w += bias[col + 3];
            }
            if (doRelu) {
                v.x = fmaxf(v.x, 0.f); v.y = fmaxf(v.y, 0.f);
                v.z = fmaxf(v.z, 0.f); v.w = fmaxf(v.w, 0.f);
            }
            *(float4*)(C + (size_t)row * N + col) = v;
        }
    }
}

// out[N] = v[K] @ W[K,N]
__global__ void vecmat_k(const float* __restrict__ v, const float* __restrict__ W,
                         float* __restrict__ out, int K, int N)
{
    int c = blockIdx.x * blockDim.x + threadIdx.x;
    if (c >= N) return;
    float s = 0.f;
    for (int k = 0; k < K; ++k) s = fmaf(v[k], W[k * N + c], s);
    out[c] = s;
}

// cnt[dst] += 1 per edge
__global__ void count_k(const int* __restrict__ dst, int E, float* __restrict__ cnt)
{
    int e = blockIdx.x * blockDim.x + threadIdx.x;
    if (e < E) atomicAdd(&cnt[dst[e]], 1.0f);
}

// agg[dst,:] += src_feat[src,:]  — 64 threads/edge, float4 gather + 4 atomics
__global__ void scatter_k(const float* __restrict__ feat, const int* __restrict__ src,
                          const int* __restrict__ dst, int E, float* __restrict__ agg)
{
    int t = blockIdx.x * blockDim.x + threadIdx.x;
    int e = t >> 6;                   // 64 threads per edge (HID/4)
    if (e >= E) return;
    int c4 = (t & 63) * 4;
    int s = src[e];
    int d = dst[e];
    float4 v = *(const float4*)(feat + (size_t)s * HID + c4);
    float* o = agg + (size_t)d * HID + c4;
    atomicAdd(o + 0, v.x);
    atomicAdd(o + 1, v.y);
    atomicAdd(o + 2, v.z);
    atomicAdd(o + 3, v.w);
}

// out = relu(agg/max(cnt,1) + bias + other)
__global__ void combine_k(const float* __restrict__ agg, const float* __restrict__ cnt,
                          const float* __restrict__ other, const float* __restrict__ bias,
                          float* __restrict__ out)
{
    int t = blockIdx.x * blockDim.x + threadIdx.x;
    if (t >= NCOMM * (HID / 4)) return;
    int i = t >> 6;
    int c4 = (t & 63) * 4;
    float inv = 1.0f / fmaxf(cnt[i], 1.0f);
    float4 a = *(const float4*)(agg + (size_t)i * HID + c4);
    float4 o = *(const float4*)(other + (size_t)i * HID + c4);
    float4 b = *(const float4*)(bias + c4);
    float4 r;
    r.x = fmaxf(fmaf(a.x, inv, o.x + b.x), 0.f);
    r.y = fmaxf(fmaf(a.y, inv, o.y + b.y), 0.f);
    r.z = fmaxf(fmaf(a.z, inv, o.z + b.z), 0.f);
    r.w = fmaxf(fmaf(a.w, inv, o.w + b.w), 0.f);
    *(float4*)(out + (size_t)i * HID + c4) = r;
}

extern "C" void kernel_launch(void* const* d_in, const int* in_sizes, int n_in,
                              void* d_out, int out_size)
{
    const float* article_x   = (const float*)d_in[0];
    const float* community_x = (const float*)d_in[1];
    const int*   e_wb  = (const int*)d_in[2];
    const int*   e_mb  = (const int*)d_in[3];
    const int*   e_int = (const int*)d_in[4];
    const float* W1  = (const float*)d_in[5];
    const float* b1  = (const float*)d_in[6];
    const float* W2  = (const float*)d_in[7];
    const float* b2  = (const float*)d_in[8];
    const float* Wl1 = (const float*)d_in[9];
    const float* bl1 = (const float*)d_in[10];
    const float* Wr1 = (const float*)d_in[11];
    const float* Wl2 = (const float*)d_in[12];
    const float* bl2 = (const float*)d_in[13];
    const float* Wr2 = (const float*)d_in[14];
    const float* Wl3 = (const float*)d_in[15];
    const float* bl3 = (const float*)d_in[16];
    const float* Wr3 = (const float*)d_in[17];
    const float* W3  = (const float*)d_in[18];
    const float* b3  = (const float*)d_in[19];

    const int Ewb  = in_sizes[2] / 2;
    const int Emb  = in_sizes[3] / 2;
    const int Eint = in_sizes[4] / 2;

    float *Wa1, *Wa2, *Wc1, *ba1, *ba2, *bc1;
    float *A1, *A2, *C1, *R3, *AGG, *CNT, *H1, *H2, *T;
    cudaGetSymbolAddress((void**)&Wa1, g_Wa1);
    cudaGetSymbolAddress((void**)&Wa2, g_Wa2);
    cudaGetSymbolAddress((void**)&Wc1, g_Wc1);
    cudaGetSymbolAddress((void**)&ba1, g_ba1);
    cudaGetSymbolAddress((void**)&ba2, g_ba2);
    cudaGetSymbolAddress((void**)&bc1, g_bc1);
    cudaGetSymbolAddress((void**)&A1,  g_A1);
    cudaGetSymbolAddress((void**)&A2,  g_A2);
    cudaGetSymbolAddress((void**)&C1,  g_C1);
    cudaGetSymbolAddress((void**)&R3,  g_R3);
    cudaGetSymbolAddress((void**)&AGG, g_AGG);
    cudaGetSymbolAddress((void**)&CNT, g_CNT);
    cudaGetSymbolAddress((void**)&H1,  g_H1);
    cudaGetSymbolAddress((void**)&H2,  g_H2);
    cudaGetSymbolAddress((void**)&T,   g_T);

    const dim3 blk(256);

    // ---- fold small weight products: Wa1=W1@Wl1, Wa2=W1@Wl2, Wc1=W2@Wr1 ----
    vecmat_k<<<1, HID>>>(b1, Wl1, ba1, PROJ, HID);
    vecmat_k<<<1, HID>>>(b1, Wl2, ba2, PROJ, HID);
    vecmat_k<<<1, HID>>>(b2, Wr1, bc1, PROJ, HID);
    dim3 gf(HID / 128, (FIN + 127) / 128);
    sgemm128<<<gf, blk>>>(W1, Wl1, nullptr, Wa1, FIN, HID, PROJ, 0);
    sgemm128<<<gf, blk>>>(W1, Wl2, nullptr, Wa2, FIN, HID, PROJ, 0);
    sgemm128<<<gf, blk>>>(W2, Wr1, nullptr, Wc1, FIN, HID, PROJ, 0);

    // ---- node projections directly to HID=256 (skip PROJ=1024 entirely) ----
    dim3 gb(HID / 128, (NART + 127) / 128);
    sgemm128<<<gb, blk>>>(article_x,   Wa1, ba1, A1, NART,  HID, FIN, 0);
    sgemm128<<<gb, blk>>>(article_x,   Wa2, ba2, A2, NART,  HID, FIN, 0);
    sgemm128<<<gb, blk>>>(community_x, Wc1, bc1, C1, NCOMM, HID, FIN, 0);
    sgemm128<<<gb, blk>>>(community_x, Wr3, nullptr, R3, NCOMM, HID, FIN, 0);

    const int combBlocks = (NCOMM * (HID / 4) + 255) / 256;

    // ---- conv1: h1 = relu(segmean_{e_wb}(A1) + bl1 + C1) ----
    cudaMemsetAsync(AGG, 0, sizeof(float) * NCOMM * HID);
    cudaMemsetAsync(CNT, 0, sizeof(float) * NCOMM);
    count_k<<<(Ewb + 255) / 256, blk>>>(e_wb + Ewb, Ewb, CNT);
    scatter_k<<<(Ewb * 64 + 255) / 256, blk>>>(A1, e_wb, e_wb + Ewb, Ewb, AGG);
    combine_k<<<combBlocks, blk>>>(AGG, CNT, C1, bl1, H1);

    // ---- conv2: h2 = relu(segmean_{e_mb}(A2) + bl2 + H1@Wr2) ----
    dim3 gm(HID / 128, (NCOMM + 127) / 128);
    sgemm128<<<gm, blk>>>(H1, Wr2, nullptr, T, NCOMM, HID, HID, 0);
    cudaMemsetAsync(AGG, 0, sizeof(float) * NCOMM * HID);
    cudaMemsetAsync(CNT, 0, sizeof(float) * NCOMM);
    count_k<<<(Emb + 255) / 256, blk>>>(e_mb + Emb, Emb, CNT);
    scatter_k<<<(Emb * 64 + 255) / 256, blk>>>(A2, e_mb, e_mb + Emb, Emb, AGG);
    combine_k<<<combBlocks, blk>>>(AGG, CNT, T, bl2, H2);

    // ---- conv3: h3 = relu(segmean_{e_int}(H2@Wl3) + bl3 + R3) ----
    sgemm128<<<gm, blk>>>(H2, Wl3, nullptr, T, NCOMM, HID, HID, 0);
    cudaMemsetAsync(AGG, 0, sizeof(float) * NCOMM * HID);
    cudaMemsetAsync(CNT, 0, sizeof(float) * NCOMM);
    count_k<<<(Eint + 255) / 256, blk>>>(e_int + Eint, Eint, CNT);
    scatter_k<<<((long)Eint * 64 + 255) / 256, blk>>>(T, e_int, e_int + Eint, Eint, AGG);
    combine_k<<<combBlocks, blk>>>(AGG, CNT, R3, bl3, H1);   // h3 -> H1 (reuse)

    // ---- out = H3 @ W3 + b3 ----
    dim3 go(NOUT / 128, (NCOMM + 127) / 128);
    sgemm128<<<go, blk>>>(H1, W3, b3, (float*)d_out, NCOMM, NOUT, HID, 0);
}

// round 10
// speedup vs baseline: 2.0104x; 2.0104x over previous
#include <cuda_runtime.h>
#include <cstdint>

#define NART  50000
#define NCOMM 50000
#define FIN   768
#define PROJ  1024
#define HID   256
#define NOUT  128

// ---------------- scratch (device globals; no allocation allowed) ----------
__device__ __align__(16) float g_Wl12T[2 * PROJ * HID];   // [Wl1^T ; Wl2^T]  [512,1024]
__device__ __align__(16) float g_Wr1T [PROJ * HID];       // Wr1^T [256,1024]
__device__ __align__(16) float g_W1T  [PROJ * FIN];       // W1^T [1024,768]
__device__ __align__(16) float g_W2T  [PROJ * FIN];       // W2^T [1024,768]
__device__ __align__(16) float g_WaT12[2 * HID * FIN];    // ([W1@Wl1]^T ; [W1@Wl2]^T) [512,768]
__device__ __align__(16) float g_WCR  [2 * HID * FIN];    // ([W2@Wr1]^T ; Wr3^T)      [512,768]
__device__ __align__(16) float g_Wr2T [HID * HID];
__device__ __align__(16) float g_Wl3T [HID * HID];
__device__ __align__(16) float g_W3T  [NOUT * HID];
__device__ __align__(16) float g_ba12 [2 * HID];          // b1@Wl1 | b1@Wl2
__device__ __align__(16) float g_bcr  [2 * HID];          // b2@Wr1 | 0
__device__ __align__(16) float g_A12  [NART * 2 * HID];   // article proj: A1 | A2
__device__ __align__(16) float g_CR   [NCOMM * 2 * HID];  // community proj: C1 | R3
__device__ __align__(16) float g_AGG  [NCOMM * HID];
__device__ __align__(16) float g_CNT  [NCOMM];
__device__ __align__(16) float g_H1   [NCOMM * HID];      // h1, later h3
__device__ __align__(16) float g_H2   [NCOMM * HID];
__device__ __align__(16) float g_T    [NCOMM * HID];

__device__ __forceinline__ float f2tf32rna(float x) {
    uint32_t r;
    asm("cvt.rna.tf32.f32 %0, %1;" : "=r"(r) : "f"(x));
    return __uint_as_float(r);
}
__device__ __forceinline__ float4 tf32x4(float4 v) {
    v.x = f2tf32rna(v.x); v.y = f2tf32rna(v.y);
    v.z = f2tf32rna(v.z); v.w = f2tf32rna(v.w);
    return v;
}

// ---------------- tf32 mma.sync GEMM: C[M,N] = A[M,K] @ BT[N,K]^T (+bias) --
// 128x128 CTA tile, BK=32, 256 threads, warp tile 32x64 (2x8 m16n8k8).
// Static smem, register-prefetch double buffering. Values rna-rounded to tf32
// at smem staging (halves quantization error vs HW truncation).
// Requires N%128==0, K%32==0; M guarded. grid = (N/128, ceil(M/128)).
#define PADK 36

__global__ void __launch_bounds__(256) mmagemm(
    const float* __restrict__ A, const float* __restrict__ BT,
    const float* __restrict__ bias, float* __restrict__ C,
    int M, int N, int K)
{
    __shared__ float As[128][PADK];   // rows are 144B = 9*16B -> float4-aligned
    __shared__ float Bs[128][PADK];
    const int tid  = threadIdx.x;
    const int wid  = tid >> 5, lane = tid & 31;
    const int g    = lane >> 2, t = lane & 3;
    const int bm   = blockIdx.y * 128, bn = blockIdx.x * 128;
    const int wm   = (wid >> 1) * 32, wn = (wid & 1) * 64;

    float acc[2][8][4];
#pragma unroll
    for (int i = 0; i < 2; ++i)
#pragma unroll
        for (int j = 0; j < 8; ++j)
#pragma unroll
            for (int k = 0; k < 4; ++k) acc[i][j][k] = 0.f;

    // per-thread staging coords: 4 float4 segments each for A and B
    int mIdx[4], kqIdx[4];
#pragma unroll
    for (int s = 0; s < 4; ++s) {
        int i = s * 256 + tid;
        mIdx[s]  = i >> 3;          // 0..127
        kqIdx[s] = (i & 7) * 4;     // 0,4,...,28
    }

    const int nCh = K >> 5;
    float4 aReg[4], bReg[4];

    auto fetch = [&](int ci) {
#pragma unroll
        for (int s = 0; s < 4; ++s) {
            const int k0 = ci * 32 + kqIdx[s];
            const int am = bm + mIdx[s];
            aReg[s] = (am < M) ? *(const float4*)(A + (size_t)am * K + k0)
                               : make_float4(0.f, 0.f, 0.f, 0.f);
            bReg[s] = *(const float4*)(BT + (size_t)(bn + mIdx[s]) * K + k0);
        }
    };

    fetch(0);
    for (int ci = 0; ci < nCh; ++ci) {
#pragma unroll
        for (int s = 0; s < 4; ++s) {
            *(float4*)&As[mIdx[s]][kqIdx[s]] = tf32x4(aReg[s]);
            *(float4*)&Bs[mIdx[s]][kqIdx[s]] = tf32x4(bReg[s]);
        }
        __syncthreads();
        if (ci + 1 < nCh) fetch(ci + 1);   // overlap next LDG with MMA

#pragma unroll
        for (int kk = 0; kk < 32; kk += 8) {
            uint32_t aF[2][4], bF[8][2];
#pragma unroll
            for (int tm = 0; tm < 2; ++tm) {
                int r = wm + tm * 16 + g;
                aF[tm][0] = __float_as_uint(As[r][kk + t]);
                aF[tm][1] = __float_as_uint(As[r + 8][kk + t]);
                aF[tm][2] = __float_as_uint(As[r][kk + t + 4]);
                aF[tm][3] = __float_as_uint(As[r + 8][kk + t + 4]);
            }
#pragma unroll
            for (int tn = 0; tn < 8; ++tn) {
                int c = wn + tn * 8 + g;
                bF[tn][0] = __float_as_uint(Bs[c][kk + t]);
                bF[tn][1] = __float_as_uint(Bs[c][kk + t + 4]);
            }
#pragma unroll
            for (int tm = 0; tm < 2; ++tm)
#pragma unroll
                for (int tn = 0; tn < 8; ++tn)
                    asm volatile(
                        "mma.sync.aligned.m16n8k8.row.col.f32.tf32.tf32.f32 "
                        "{%0,%1,%2,%3}, {%4,%5,%6,%7}, {%8,%9}, {%0,%1,%2,%3};"
                        : "+f"(acc[tm][tn][0]), "+f"(acc[tm][tn][1]),
                          "+f"(acc[tm][tn][2]), "+f"(acc[tm][tn][3])
                        : "r"(aF[tm][0]), "r"(aF[tm][1]), "r"(aF[tm][2]), "r"(aF[tm][3]),
                          "r"(bF[tn][0]), "r"(bF[tn][1]));
        }
        __syncthreads();
    }

    // epilogue
#pragma unroll
    for (int tm = 0; tm < 2; ++tm)
#pragma unroll
        for (int half = 0; half < 2; ++half) {
            int row = bm + wm + tm * 16 + g + half * 8;
            if (row >= M) continue;
            float* cr = C + (size_t)row * N + bn + wn;
#pragma unroll
            for (int tn = 0; tn < 8; ++tn) {
                int col = tn * 8 + 2 * t;
                float2 v;
                v.x = acc[tm][tn][half * 2 + 0];
                v.y = acc[tm][tn][half * 2 + 1];
                if (bias) {
                    v.x += bias[bn + wn + col];
                    v.y += bias[bn + wn + col + 1];
                }
                *(float2*)(cr + col) = v;
            }
        }
}

// ---------------- fp32 SIMT SGEMM (for the weight folds; proven in R1) -----
// C[M,N] = A[M,K] @ B[K,N] (+bias). N%128==0, K%8==0, M guarded.
__global__ void __launch_bounds__(256) sgemm128(
    const float* __restrict__ A, const float* __restrict__ B,
    const float* __restrict__ bias, float* __restrict__ C,
    int M, int N, int K, int doRelu)
{
    __shared__ float As[8][132];
    __shared__ float Bs[8][128];
    const int tid = threadIdx.x;
    const int bm = blockIdx.y * 128;
    const int bn = blockIdx.x * 128;
    const int tx = tid & 15;
    const int ty = tid >> 4;

    float acc[8][8];
#pragma unroll
    for (int i = 0; i < 8; ++i)
#pragma unroll
        for (int j = 0; j < 8; ++j) acc[i][j] = 0.f;

    const int aRow = tid >> 1;
    const int aCol = (tid & 1) * 4;
    const int bRow = tid >> 5;
    const int bCol = (tid & 31) * 4;
    const int gARow = bm + aRow;
    const bool aOk = (gARow < M);
    const float* aPtr = A + (size_t)gARow * K + aCol;

    for (int k0 = 0; k0 < K; k0 += 8) {
        float4 av = make_float4(0.f, 0.f, 0.f, 0.f);
        if (aOk) av = *(const float4*)(aPtr + k0);
        As[aCol + 0][aRow] = av.x;
        As[aCol + 1][aRow] = av.y;
        As[aCol + 2][aRow] = av.z;
        As[aCol + 3][aRow] = av.w;
        float4 bv = *(const float4*)(B + (size_t)(k0 + bRow) * N + bn + bCol);
        *(float4*)(&Bs[bRow][bCol]) = bv;
        __syncthreads();
#pragma unroll
        for (int kk = 0; kk < 8; ++kk) {
            float ar[8], br[8];
            float4 a0 = *(const float4*)(&As[kk][ty * 8]);
            float4 a1 = *(const float4*)(&As[kk][ty * 8 + 4]);
            float4 b0 = *(const float4*)(&Bs[kk][tx * 8]);
            float4 b1 = *(const float4*)(&Bs[kk][tx * 8 + 4]);
            ar[0]=a0.x; ar[1]=a0.y; ar[2]=a0.z; ar[3]=a0.w;
            ar[4]=a1.x; ar[5]=a1.y; ar[6]=a1.z; ar[7]=a1.w;
            br[0]=b0.x; br[1]=b0.y; br[2]=b0.z; br[3]=b0.w;
            br[4]=b1.x; br[5]=b1.y; br[6]=b1.z; br[7]=b1.w;
#pragma unroll
            for (int i = 0; i < 8; ++i)
#pragma unroll
                for (int j = 0; j < 8; ++j)
                    acc[i][j] = fmaf(ar[i], br[j], acc[i][j]);
        }
        __syncthreads();
    }

#pragma unroll
    for (int i = 0; i < 8; ++i) {
        int row = bm + ty * 8 + i;
        if (row >= M) continue;
#pragma unroll
        for (int j = 0; j < 8; j += 4) {
            int col = bn + tx * 8 + j;
            float4 v;
            v.x = acc[i][j + 0]; v.y = acc[i][j + 1];
            v.z = acc[i][j + 2]; v.w = acc[i][j + 3];
            if (bias) {
                v.x += bias[col + 0]; v.y += bias[col + 1];
                v.z += bias[col + 2]; v.w += bias[col + 3];
            }
            if (doRelu) {
                v.x = fmaxf(v.x, 0.f); v.y = fmaxf(v.y, 0.f);
                v.z = fmaxf(v.z, 0.f); v.w = fmaxf(v.w, 0.f);
            }
            *(float4*)(C + (size_t)row * N + col) = v;
        }
    }
}

// ---------------- small helpers --------------------------------------------
__global__ void transpose_k(const float* __restrict__ in, float* __restrict__ out,
                            int R, int C)
{
    int t = blockIdx.x * blockDim.x + threadIdx.x;
    if (t >= R * C) return;
    int r = t / C, c = t % C;
    out[(size_t)c * R + r] = in[(size_t)r * C + c];
}

__global__ void vecmat_k(const float* __restrict__ v, const float* __restrict__ W,
                         float* __restrict__ out, int K, int N)
{
    int c = blockIdx.x * blockDim.x + threadIdx.x;
    if (c >= N) return;
    float s = 0.f;
    for (int k = 0; k < K; ++k) s = fmaf(v[k], W[k * N + c], s);
    out[c] = s;
}

__global__ void count_k(const int* __restrict__ dst, int E, float* __restrict__ cnt)
{
    int e = blockIdx.x * blockDim.x + threadIdx.x;
    if (e < E) atomicAdd(&cnt[dst[e]], 1.0f);
}

// agg[dst,:HID] += feat[src*ld : +HID] — 64 threads/edge, float4 gather + 4 atomics
__global__ void scatter_k(const float* __restrict__ feat, int ld,
                          const int* __restrict__ src, const int* __restrict__ dst,
                          int E, float* __restrict__ agg)
{
    int tt = blockIdx.x * blockDim.x + threadIdx.x;
    int e = tt >> 6;
    if (e >= E) return;
    int c4 = (tt & 63) * 4;
    float4 v = *(const float4*)(feat + (size_t)src[e] * ld + c4);
    float* o = agg + (size_t)dst[e] * HID + c4;
    atomicAdd(o + 0, v.x);
    atomicAdd(o + 1, v.y);
    atomicAdd(o + 2, v.z);
    atomicAdd(o + 3, v.w);
}

// out = relu(agg/max(cnt,1) + bias + other)  (other has leading dim ldO)
__global__ void combine_k(const float* __restrict__ agg, const float* __restrict__ cnt,
                          const float* __restrict__ other, int ldO,
                          const float* __restrict__ bias, float* __restrict__ out)
{
    int t = blockIdx.x * blockDim.x + threadIdx.x;
    if (t >= NCOMM * (HID / 4)) return;
    int i = t >> 6;
    int c4 = (t & 63) * 4;
    float inv = 1.0f / fmaxf(cnt[i], 1.0f);
    float4 a = *(const float4*)(agg + (size_t)i * HID + c4);
    float4 o = *(const float4*)(other + (size_t)i * ldO + c4);
    float4 b = *(const float4*)(bias + c4);
    float4 r;
    r.x = fmaxf(fmaf(a.x, inv, o.x + b.x), 0.f);
    r.y = fmaxf(fmaf(a.y, inv, o.y + b.y), 0.f);
    r.z = fmaxf(fmaf(a.z, inv, o.z + b.z), 0.f);
    r.w = fmaxf(fmaf(a.w, inv, o.w + b.w), 0.f);
    *(float4*)(out + (size_t)i * HID + c4) = r;
}

// ---------------- launch ----------------------------------------------------
extern "C" void kernel_launch(void* const* d_in, const int* in_sizes, int n_in,
                              void* d_out, int out_size)
{
    const float* article_x   = (const float*)d_in[0];
    const float* community_x = (const float*)d_in[1];
    const int*   e_wb  = (const int*)d_in[2];
    const int*   e_mb  = (const int*)d_in[3];
    const int*   e_int = (const int*)d_in[4];
    const float* W1  = (const float*)d_in[5];
    const float* b1  = (const float*)d_in[6];
    const float* W2  = (const float*)d_in[7];
    const float* b2  = (const float*)d_in[8];
    const float* Wl1 = (const float*)d_in[9];
    const float* bl1 = (const float*)d_in[10];
    const float* Wr1 = (const float*)d_in[11];
    const float* Wl2 = (const float*)d_in[12];
    const float* bl2 = (const float*)d_in[13];
    const float* Wr2 = (const float*)d_in[14];
    const float* Wl3 = (const float*)d_in[15];
    const float* bl3 = (const float*)d_in[16];
    const float* Wr3 = (const float*)d_in[17];
    const float* W3  = (const float*)d_in[18];
    const float* b3  = (const float*)d_in[19];

    const int Ewb  = in_sizes[2] / 2;
    const int Emb  = in_sizes[3] / 2;
    const int Eint = in_sizes[4] / 2;

    float *Wl12T,*Wr1T,*W1T,*W2T,*WaT12,*WCR,*Wr2T,*Wl3T,*W3T,*ba12,*bcr;
    float *A12,*CR,*AGG,*CNT,*H1,*H2,*T;
    cudaGetSymbolAddress((void**)&Wl12T, g_Wl12T);
    cudaGetSymbolAddress((void**)&Wr1T,  g_Wr1T);
    cudaGetSymbolAddress((void**)&W1T,   g_W1T);
    cudaGetSymbolAddress((void**)&W2T,   g_W2T);
    cudaGetSymbolAddress((void**)&WaT12, g_WaT12);
    cudaGetSymbolAddress((void**)&WCR,   g_WCR);
    cudaGetSymbolAddress((void**)&Wr2T,  g_Wr2T);
    cudaGetSymbolAddress((void**)&Wl3T,  g_Wl3T);
    cudaGetSymbolAddress((void**)&W3T,   g_W3T);
    cudaGetSymbolAddress((void**)&ba12,  g_ba12);
    cudaGetSymbolAddress((void**)&bcr,   g_bcr);
    cudaGetSymbolAddress((void**)&A12,   g_A12);
    cudaGetSymbolAddress((void**)&CR,    g_CR);
    cudaGetSymbolAddress((void**)&AGG,   g_AGG);
    cudaGetSymbolAddress((void**)&CNT,   g_CNT);
    cudaGetSymbolAddress((void**)&H1,    g_H1);
    cudaGetSymbolAddress((void**)&H2,    g_H2);
    cudaGetSymbolAddress((void**)&T,     g_T);

    const dim3 blk(256);

    // ---- weight transposes ----
    transpose_k<<<(PROJ*HID + 255)/256, blk>>>(Wl1, Wl12T, PROJ, HID);
    transpose_k<<<(PROJ*HID + 255)/256, blk>>>(Wl2, Wl12T + PROJ*HID, PROJ, HID);
    transpose_k<<<(PROJ*HID + 255)/256, blk>>>(Wr1, Wr1T, PROJ, HID);
    transpose_k<<<(FIN*PROJ + 255)/256, blk>>>(W1, W1T, FIN, PROJ);   // W1^T [1024,768]
    transpose_k<<<(FIN*PROJ + 255)/256, blk>>>(W2, W2T, FIN, PROJ);   // W2^T [1024,768]
    transpose_k<<<(FIN*HID + 255)/256,  blk>>>(Wr3, WCR + HID*FIN, FIN, HID); // Wr3^T rows 256-511
    transpose_k<<<(HID*HID + 255)/256,  blk>>>(Wr2, Wr2T, HID, HID);
    transpose_k<<<(HID*HID + 255)/256,  blk>>>(Wl3, Wl3T, HID, HID);
    transpose_k<<<(HID*NOUT + 255)/256, blk>>>(W3,  W3T,  HID, NOUT);

    // ---- folded biases (fp32) ----
    cudaMemsetAsync(bcr, 0, sizeof(float) * 2 * HID);
    vecmat_k<<<1, HID>>>(b1, Wl1, ba12,       PROJ, HID);
    vecmat_k<<<1, HID>>>(b1, Wl2, ba12 + HID, PROJ, HID);
    vecmat_k<<<1, HID>>>(b2, Wr1, bcr,        PROJ, HID);

    // ---- weight folds in FULL FP32 (largest-K pass; keep exact) ----
    // WaT12[512,768] = Wl12T[512,1024] @ W1T[1024,768]; WCR rows 0-255 likewise.
    dim3 gF1(FIN/128, 4);  // M=512
    dim3 gF2(FIN/128, 2);  // M=256
    sgemm128<<<gF1, blk>>>(Wl12T, W1T, nullptr, WaT12, 2*HID, FIN, PROJ, 0);
    sgemm128<<<gF2, blk>>>(Wr1T,  W2T, nullptr, WCR,   HID,   FIN, PROJ, 0);

    // ---- node projections (tf32 tensor, rna-rounded), fused N=512 ----
    dim3 gBig(4, (NART + 127)/128);
    mmagemm<<<gBig, blk>>>(article_x,   WaT12, ba12, A12, NART,  2*HID, FIN);
    mmagemm<<<gBig, blk>>>(community_x, WCR,   bcr,  CR,  NCOMM, 2*HID, FIN);

    const int combBlocks = (NCOMM * (HID/4) + 255)/256;
    dim3 gMid(2, (NCOMM + 127)/128);

    // ---- conv1: h1 = relu(segmean_{e_wb}(A1) + bl1 + C1) ----
    cudaMemsetAsync(AGG, 0, sizeof(float) * NCOMM * HID);
    cudaMemsetAsync(CNT, 0, sizeof(float) * NCOMM);
    count_k<<<(Ewb + 255)/256, blk>>>(e_wb + Ewb, Ewb, CNT);
    scatter_k<<<(Ewb*64 + 255)/256, blk>>>(A12, 2*HID, e_wb, e_wb + Ewb, Ewb, AGG);
    combine_k<<<combBlocks, blk>>>(AGG, CNT, CR, 2*HID, bl1, H1);

    // ---- conv2: h2 = relu(segmean_{e_mb}(A2) + bl2 + H1@Wr2) ----
    mmagemm<<<gMid, blk>>>(H1, Wr2T, nullptr, T, NCOMM, HID, HID);
    cudaMemsetAsync(AGG, 0, sizeof(float) * NCOMM * HID);
    cudaMemsetAsync(CNT, 0, sizeof(float) * NCOMM);
    count_k<<<(Emb + 255)/256, blk>>>(e_mb + Emb, Emb, CNT);
    scatter_k<<<(Emb*64 + 255)/256, blk>>>(A12 + HID, 2*HID, e_mb, e_mb + Emb, Emb, AGG);
    combine_k<<<combBlocks, blk>>>(AGG, CNT, T, HID, bl2, H2);

    // ---- conv3: h3 = relu(segmean_{e_int}(H2@Wl3) + bl3 + R3) ----
    mmagemm<<<gMid, blk>>>(H2, Wl3T, nullptr, T, NCOMM, HID, HID);
    cudaMemsetAsync(AGG, 0, sizeof(float) * NCOMM * HID);
    cudaMemsetAsync(CNT, 0, sizeof(float) * NCOMM);
    count_k<<<(Eint + 255)/256, blk>>>(e_int + Eint, Eint, CNT);
    scatter_k<<<((long)Eint*64 + 255)/256, blk>>>(T, HID, e_int, e_int + Eint, Eint, AGG);
    combine_k<<<combBlocks, blk>>>(AGG, CNT, CR + HID, 2*HID, bl3, H1);

    // ---- out = H3 @ W3 + b3 ----
    dim3 gOut(1, (NCOMM + 127)/128);
    mmagemm<<<gOut, blk>>>(H1, W3T, b3, (float*)d_out, NCOMM, NOUT, HID);
}

// round 11
// speedup vs baseline: 2.3728x; 1.1802x over previous
#include <cuda_runtime.h>
#include <cstdint>

#define NART  50000
#define NCOMM 50000
#define FIN   768
#define PROJ  1024
#define HID   256
#define NOUT  128

// ---------------- scratch (device globals; no allocation allowed) ----------
__device__ __align__(16) float g_Wl12T[2 * PROJ * HID];   // [Wl1^T ; Wl2^T]  [512,1024]
__device__ __align__(16) float g_Wr1T [PROJ * HID];       // Wr1^T [256,1024]
__device__ __align__(16) float g_W1T  [PROJ * FIN];       // W1^T [1024,768]
__device__ __align__(16) float g_W2T  [PROJ * FIN];       // W2^T [1024,768]
__device__ __align__(16) float g_WaT12[2 * HID * FIN];    // ([W1@Wl1]^T ; [W1@Wl2]^T) [512,768]
__device__ __align__(16) float g_WCR  [2 * HID * FIN];    // ([W2@Wr1]^T ; Wr3^T)      [512,768]
__device__ __align__(16) float g_Wr2T [HID * HID];
__device__ __align__(16) float g_Wl3T [HID * HID];
__device__ __align__(16) float g_W3T  [NOUT * HID];
__device__ __align__(16) float g_ba12 [2 * HID];          // b1@Wl1 | b1@Wl2
__device__ __align__(16) float g_bcr  [2 * HID];          // b2@Wr1 | 0
__device__ __align__(16) float g_A12  [NART * 2 * HID];   // article proj: A1 | A2
__device__ __align__(16) float g_CR   [NCOMM * 2 * HID];  // community proj: C1 | R3
__device__ __align__(16) float g_AGG  [NCOMM * HID];
__device__ __align__(16) float g_CNT  [NCOMM];
__device__ __align__(16) float g_H1   [NCOMM * HID];      // h1, later h3
__device__ __align__(16) float g_H2   [NCOMM * HID];
__device__ __align__(16) float g_T    [NCOMM * HID];

__device__ __forceinline__ float f2tf32rna(float x) {
    uint32_t r;
    asm("cvt.rna.tf32.f32 %0, %1;" : "=r"(r) : "f"(x));
    return __uint_as_float(r);
}
__device__ __forceinline__ float4 tf32x4(float4 v) {
    v.x = f2tf32rna(v.x); v.y = f2tf32rna(v.y);
    v.z = f2tf32rna(v.z); v.w = f2tf32rna(v.w);
    return v;
}

// ---------------- tf32 mma.sync GEMM: C[M,N] = A[M,K] @ BT[N,K]^T (+bias) --
// 128x128 CTA tile, BK=32, 256 threads, warp tile 32x64 (2x8 m16n8k8).
// Static smem, register-prefetch double buffering. Values rna-rounded to tf32
// at smem staging (halves quantization error vs HW truncation).
// Requires N%128==0, K%32==0; M guarded. grid = (N/128, ceil(M/128)).
#define PADK 36

__global__ void __launch_bounds__(256) mmagemm(
    const float* __restrict__ A, const float* __restrict__ BT,
    const float* __restrict__ bias, float* __restrict__ C,
    int M, int N, int K)
{
    __shared__ float As[128][PADK];   // rows are 144B = 9*16B -> float4-aligned
    __shared__ float Bs[128][PADK];
    const int tid  = threadIdx.x;
    const int wid  = tid >> 5, lane = tid & 31;
    const int g    = lane >> 2, t = lane & 3;
    const int bm   = blockIdx.y * 128, bn = blockIdx.x * 128;
    const int wm   = (wid >> 1) * 32, wn = (wid & 1) * 64;

    float acc[2][8][4];
#pragma unroll
    for (int i = 0; i < 2; ++i)
#pragma unroll
        for (int j = 0; j < 8; ++j)
#pragma unroll
            for (int k = 0; k < 4; ++k) acc[i][j][k] = 0.f;

    // per-thread staging coords: 4 float4 segments each for A and B
    int mIdx[4], kqIdx[4];
#pragma unroll
    for (int s = 0; s < 4; ++s) {
        int i = s * 256 + tid;
        mIdx[s]  = i >> 3;          // 0..127
        kqIdx[s] = (i & 7) * 4;     // 0,4,...,28
    }

    const int nCh = K >> 5;
    float4 aReg[4], bReg[4];

    auto fetch = [&](int ci) {
#pragma unroll
        for (int s = 0; s < 4; ++s) {
            const int k0 = ci * 32 + kqIdx[s];
            const int am = bm + mIdx[s];
            aReg[s] = (am < M) ? *(const float4*)(A + (size_t)am * K + k0)
                               : make_float4(0.f, 0.f, 0.f, 0.f);
            bReg[s] = *(const float4*)(BT + (size_t)(bn + mIdx[s]) * K + k0);
        }
    };

    fetch(0);
    for (int ci = 0; ci < nCh; ++ci) {
#pragma unroll
        for (int s = 0; s < 4; ++s) {
            *(float4*)&As[mIdx[s]][kqIdx[s]] = tf32x4(aReg[s]);
            *(float4*)&Bs[mIdx[s]][kqIdx[s]] = tf32x4(bReg[s]);
        }
        __syncthreads();
        if (ci + 1 < nCh) fetch(ci + 1);   // overlap next LDG with MMA

#pragma unroll
        for (int kk = 0; kk < 32; kk += 8) {
            uint32_t aF[2][4], bF[8][2];
#pragma unroll
            for (int tm = 0; tm < 2; ++tm) {
                int r = wm + tm * 16 + g;
                aF[tm][0] = __float_as_uint(As[r][kk + t]);
                aF[tm][1] = __float_as_uint(As[r + 8][kk + t]);
                aF[tm][2] = __float_as_uint(As[r][kk + t + 4]);
                aF[tm][3] = __float_as_uint(As[r + 8][kk + t + 4]);
            }
#pragma unroll
            for (int tn = 0; tn < 8; ++tn) {
                int c = wn + tn * 8 + g;
                bF[tn][0] = __float_as_uint(Bs[c][kk + t]);
                bF[tn][1] = __float_as_uint(Bs[c][kk + t + 4]);
            }
#pragma unroll
            for (int tm = 0; tm < 2; ++tm)
#pragma unroll
                for (int tn = 0; tn < 8; ++tn)
                    asm volatile(
                        "mma.sync.aligned.m16n8k8.row.col.f32.tf32.tf32.f32 "
                        "{%0,%1,%2,%3}, {%4,%5,%6,%7}, {%8,%9}, {%0,%1,%2,%3};"
                        : "+f"(acc[tm][tn][0]), "+f"(acc[tm][tn][1]),
                          "+f"(acc[tm][tn][2]), "+f"(acc[tm][tn][3])
                        : "r"(aF[tm][0]), "r"(aF[tm][1]), "r"(aF[tm][2]), "r"(aF[tm][3]),
                          "r"(bF[tn][0]), "r"(bF[tn][1]));
        }
        __syncthreads();
    }

    // epilogue
#pragma unroll
    for (int tm = 0; tm < 2; ++tm)
#pragma unroll
        for (int half = 0; half < 2; ++half) {
            int row = bm + wm + tm * 16 + g + half * 8;
            if (row >= M) continue;
            float* cr = C + (size_t)row * N + bn + wn;
#pragma unroll
            for (int tn = 0; tn < 8; ++tn) {
                int col = tn * 8 + 2 * t;
                float2 v;
                v.x = acc[tm][tn][half * 2 + 0];
                v.y = acc[tm][tn][half * 2 + 1];
                if (bias) {
                    v.x += bias[bn + wn + col];
                    v.y += bias[bn + wn + col + 1];
                }
                *(float2*)(cr + col) = v;
            }
        }
}

// ---------------- fp32 SIMT SGEMM (for the weight folds; proven in R1) -----
// C[M,N] = A[M,K] @ B[K,N] (+bias). N%128==0, K%8==0, M guarded.
__global__ void __launch_bounds__(256) sgemm128(
    const float* __restrict__ A, const float* __restrict__ B,
    const float* __restrict__ bias, float* __restrict__ C,
    int M, int N, int K, int doRelu)
{
    __shared__ float As[8][132];
    __shared__ float Bs[8][128];
    const int tid = threadIdx.x;
    const int bm = blockIdx.y * 128;
    const int bn = blockIdx.x * 128;
    const int tx = tid & 15;
    const int ty = tid >> 4;

    float acc[8][8];
#pragma unroll
    for (int i = 0; i < 8; ++i)
#pragma unroll
        for (int j = 0; j < 8; ++j) acc[i][j] = 0.f;

    const int aRow = tid >> 1;
    const int aCol = (tid & 1) * 4;
    const int bRow = tid >> 5;
    const int bCol = (tid & 31) * 4;
    const int gARow = bm + aRow;
    const bool aOk = (gARow < M);
    const float* aPtr = A + (size_t)gARow * K + aCol;

    for (int k0 = 0; k0 < K; k0 += 8) {
        float4 av = make_float4(0.f, 0.f, 0.f, 0.f);
        if (aOk) av = *(const float4*)(aPtr + k0);
        As[aCol + 0][aRow] = av.x;
        As[aCol + 1][aRow] = av.y;
        As[aCol + 2][aRow] = av.z;
        As[aCol + 3][aRow] = av.w;
        float4 bv = *(const float4*)(B + (size_t)(k0 + bRow) * N + bn + bCol);
        *(float4*)(&Bs[bRow][bCol]) = bv;
        __syncthreads();
#pragma unroll
        for (int kk = 0; kk < 8; ++kk) {
            float ar[8], br[8];
            float4 a0 = *(const float4*)(&As[kk][ty * 8]);
            float4 a1 = *(const float4*)(&As[kk][ty * 8 + 4]);
            float4 b0 = *(const float4*)(&Bs[kk][tx * 8]);
            float4 b1 = *(const float4*)(&Bs[kk][tx * 8 + 4]);
            ar[0]=a0.x; ar[1]=a0.y; ar[2]=a0.z; ar[3]=a0.w;
            ar[4]=a1.x; ar[5]=a1.y; ar[6]=a1.z; ar[7]=a1.w;
            br[0]=b0.x; br[1]=b0.y; br[2]=b0.z; br[3]=b0.w;
            br[4]=b1.x; br[5]=b1.y; br[6]=b1.z; br[7]=b1.w;
#pragma unroll
            for (int i = 0; i < 8; ++i)
#pragma unroll
                for (int j = 0; j < 8; ++j)
                    acc[i][j] = fmaf(ar[i], br[j], acc[i][j]);
        }
        __syncthreads();
    }

#pragma unroll
    for (int i = 0; i < 8; ++i) {
        int row = bm + ty * 8 + i;
        if (row >= M) continue;
#pragma unroll
        for (int j = 0; j < 8; j += 4) {
            int col = bn + tx * 8 + j;
            float4 v;
            v.x = acc[i][j + 0]; v.y = acc[i][j + 1];
            v.z = acc[i][j + 2]; v.w = acc[i][j + 3];
            if (bias) {
                v.x += bias[col + 0]; v.y += bias[col + 1];
                v.z += bias[col + 2]; v.w += bias[col + 3];
            }
            if (doRelu) {
                v.x = fmaxf(v.x, 0.f); v.y = fmaxf(v.y, 0.f);
                v.z = fmaxf(v.z, 0.f); v.w = fmaxf(v.w, 0.f);
            }
            *(float4*)(C + (size_t)row * N + col) = v;
        }
    }
}

// ---------------- small helpers --------------------------------------------
__global__ void transpose_k(const float* __restrict__ in, float* __restrict__ out,
                            int R, int C)
{
    int t = blockIdx.x * blockDim.x + threadIdx.x;
    if (t >= R * C) return;
    int r = t / C, c = t % C;
    out[(size_t)c * R + r] = in[(size_t)r * C + c];
}

__global__ void vecmat_k(const float* __restrict__ v, const float* __restrict__ W,
                         float* __restrict__ out, int K, int N)
{
    int c = blockIdx.x * blockDim.x + threadIdx.x;
    if (c >= N) return;
    float s = 0.f;
    for (int k = 0; k < K; ++k) s = fmaf(v[k], W[k * N + c], s);
    out[c] = s;
}

__global__ void count_k(const int* __restrict__ dst, int E, float* __restrict__ cnt)
{
    int e = blockIdx.x * blockDim.x + threadIdx.x;
    if (e < E) atomicAdd(&cnt[dst[e]], 1.0f);
}

// agg[dst,:HID] += feat[src*ld : +HID] — 64 threads/edge, one vector atomic
__global__ void scatter_k(const float* __restrict__ feat, int ld,
                          const int* __restrict__ src, const int* __restrict__ dst,
                          int E, float* __restrict__ agg)
{
    int tt = blockIdx.x * blockDim.x + threadIdx.x;
    int e = tt >> 6;
    if (e >= E) return;
    int c4 = (tt & 63) * 4;
    float4 v = *(const float4*)(feat + (size_t)src[e] * ld + c4);
    float4* o = (float4*)(agg + (size_t)dst[e] * HID + c4);
    atomicAdd(o, v);   // sm_90+: RED.E.ADD.F32.V4 — 1 L2 atomic op instead of 4
}

// out = relu(agg/max(cnt,1) + bias + other)  (other has leading dim ldO)
__global__ void combine_k(const float* __restrict__ agg, const float* __restrict__ cnt,
                          const float* __restrict__ other, int ldO,
                          const float* __restrict__ bias, float* __restrict__ out)
{
    int t = blockIdx.x * blockDim.x + threadIdx.x;
    if (t >= NCOMM * (HID / 4)) return;
    int i = t >> 6;
    int c4 = (t & 63) * 4;
    float inv = 1.0f / fmaxf(cnt[i], 1.0f);
    float4 a = *(const float4*)(agg + (size_t)i * HID + c4);
    float4 o = *(const float4*)(other + (size_t)i * ldO + c4);
    float4 b = *(const float4*)(bias + c4);
    float4 r;
    r.x = fmaxf(fmaf(a.x, inv, o.x + b.x), 0.f);
    r.y = fmaxf(fmaf(a.y, inv, o.y + b.y), 0.f);
    r.z = fmaxf(fmaf(a.z, inv, o.z + b.z), 0.f);
    r.w = fmaxf(fmaf(a.w, inv, o.w + b.w), 0.f);
    *(float4*)(out + (size_t)i * HID + c4) = r;
}

// ---------------- launch ----------------------------------------------------
extern "C" void kernel_launch(void* const* d_in, const int* in_sizes, int n_in,
                              void* d_out, int out_size)
{
    const float* article_x   = (const float*)d_in[0];
    const float* community_x = (const float*)d_in[1];
    const int*   e_wb  = (const int*)d_in[2];
    const int*   e_mb  = (const int*)d_in[3];
    const int*   e_int = (const int*)d_in[4];
    const float* W1  = (const float*)d_in[5];
    const float* b1  = (const float*)d_in[6];
    const float* W2  = (const float*)d_in[7];
    const float* b2  = (const float*)d_in[8];
    const float* Wl1 = (const float*)d_in[9];
    const float* bl1 = (const float*)d_in[10];
    const float* Wr1 = (const float*)d_in[11];
    const float* Wl2 = (const float*)d_in[12];
    const float* bl2 = (const float*)d_in[13];
    const float* Wr2 = (const float*)d_in[14];
    const float* Wl3 = (const float*)d_in[15];
    const float* bl3 = (const float*)d_in[16];
    const float* Wr3 = (const float*)d_in[17];
    const float* W3  = (const float*)d_in[18];
    const float* b3  = (const float*)d_in[19];

    const int Ewb  = in_sizes[2] / 2;
    const int Emb  = in_sizes[3] / 2;
    const int Eint = in_sizes[4] / 2;

    float *Wl12T,*Wr1T,*W1T,*W2T,*WaT12,*WCR,*Wr2T,*Wl3T,*W3T,*ba12,*bcr;
    float *A12,*CR,*AGG,*CNT,*H1,*H2,*T;
    cudaGetSymbolAddress((void**)&Wl12T, g_Wl12T);
    cudaGetSymbolAddress((void**)&Wr1T,  g_Wr1T);
    cudaGetSymbolAddress((void**)&W1T,   g_W1T);
    cudaGetSymbolAddress((void**)&W2T,   g_W2T);
    cudaGetSymbolAddress((void**)&WaT12, g_WaT12);
    cudaGetSymbolAddress((void**)&WCR,   g_WCR);
    cudaGetSymbolAddress((void**)&Wr2T,  g_Wr2T);
    cudaGetSymbolAddress((void**)&Wl3T,  g_Wl3T);
    cudaGetSymbolAddress((void**)&W3T,   g_W3T);
    cudaGetSymbolAddress((void**)&ba12,  g_ba12);
    cudaGetSymbolAddress((void**)&bcr,   g_bcr);
    cudaGetSymbolAddress((void**)&A12,   g_A12);
    cudaGetSymbolAddress((void**)&CR,    g_CR);
    cudaGetSymbolAddress((void**)&AGG,   g_AGG);
    cudaGetSymbolAddress((void**)&CNT,   g_CNT);
    cudaGetSymbolAddress((void**)&H1,    g_H1);
    cudaGetSymbolAddress((void**)&H2,    g_H2);
    cudaGetSymbolAddress((void**)&T,     g_T);

    const dim3 blk(256);

    // ---- weight transposes ----
    transpose_k<<<(PROJ*HID + 255)/256, blk>>>(Wl1, Wl12T, PROJ, HID);
    transpose_k<<<(PROJ*HID + 255)/256, blk>>>(Wl2, Wl12T + PROJ*HID, PROJ, HID);
    transpose_k<<<(PROJ*HID + 255)/256, blk>>>(Wr1, Wr1T, PROJ, HID);
    transpose_k<<<(FIN*PROJ + 255)/256, blk>>>(W1, W1T, FIN, PROJ);   // W1^T [1024,768]
    transpose_k<<<(FIN*PROJ + 255)/256, blk>>>(W2, W2T, FIN, PROJ);   // W2^T [1024,768]
    transpose_k<<<(FIN*HID + 255)/256,  blk>>>(Wr3, WCR + HID*FIN, FIN, HID); // Wr3^T rows 256-511
    transpose_k<<<(HID*HID + 255)/256,  blk>>>(Wr2, Wr2T, HID, HID);
    transpose_k<<<(HID*HID + 255)/256,  blk>>>(Wl3, Wl3T, HID, HID);
    transpose_k<<<(HID*NOUT + 255)/256, blk>>>(W3,  W3T,  HID, NOUT);

    // ---- folded biases (fp32) ----
    cudaMemsetAsync(bcr, 0, sizeof(float) * 2 * HID);
    vecmat_k<<<1, HID>>>(b1, Wl1, ba12,       PROJ, HID);
    vecmat_k<<<1, HID>>>(b1, Wl2, ba12 + HID, PROJ, HID);
    vecmat_k<<<1, HID>>>(b2, Wr1, bcr,        PROJ, HID);

    // ---- weight folds in FULL FP32 (largest-K pass; keep exact) ----
    dim3 gF1(FIN/128, 4);  // M=512
    dim3 gF2(FIN/128, 2);  // M=256
    sgemm128<<<gF1, blk>>>(Wl12T, W1T, nullptr, WaT12, 2*HID, FIN, PROJ, 0);
    sgemm128<<<gF2, blk>>>(Wr1T,  W2T, nullptr, WCR,   HID,   FIN, PROJ, 0);

    // ---- node projections (tf32 tensor, rna-rounded), fused N=512 ----
    dim3 gBig(4, (NART + 127)/128);
    mmagemm<<<gBig, blk>>>(article_x,   WaT12, ba12, A12, NART,  2*HID, FIN);
    mmagemm<<<gBig, blk>>>(community_x, WCR,   bcr,  CR,  NCOMM, 2*HID, FIN);

    const int combBlocks = (NCOMM * (HID/4) + 255)/256;
    dim3 gMid(2, (NCOMM + 127)/128);

    // ---- conv1: h1 = relu(segmean_{e_wb}(A1) + bl1 + C1) ----
    cudaMemsetAsync(AGG, 0, sizeof(float) * NCOMM * HID);
    cudaMemsetAsync(CNT, 0, sizeof(float) * NCOMM);
    count_k<<<(Ewb + 255)/256, blk>>>(e_wb + Ewb, Ewb, CNT);
    scatter_k<<<(Ewb*64 + 255)/256, blk>>>(A12, 2*HID, e_wb, e_wb + Ewb, Ewb, AGG);
    combine_k<<<combBlocks, blk>>>(AGG, CNT, CR, 2*HID, bl1, H1);

    // ---- conv2: h2 = relu(segmean_{e_mb}(A2) + bl2 + H1@Wr2) ----
    mmagemm<<<gMid, blk>>>(H1, Wr2T, nullptr, T, NCOMM, HID, HID);
    cudaMemsetAsync(AGG, 0, sizeof(float) * NCOMM * HID);
    cudaMemsetAsync(CNT, 0, sizeof(float) * NCOMM);
    count_k<<<(Emb + 255)/256, blk>>>(e_mb + Emb, Emb, CNT);
    scatter_k<<<(Emb*64 + 255)/256, blk>>>(A12 + HID, 2*HID, e_mb, e_mb + Emb, Emb, AGG);
    combine_k<<<combBlocks, blk>>>(AGG, CNT, T, HID, bl2, H2);

    // ---- conv3: h3 = relu(segmean_{e_int}(H2@Wl3) + bl3 + R3) ----
    mmagemm<<<gMid, blk>>>(H2, Wl3T, nullptr, T, NCOMM, HID, HID);
    cudaMemsetAsync(AGG, 0, sizeof(float) * NCOMM * HID);
    cudaMemsetAsync(CNT, 0, sizeof(float) * NCOMM);
    count_k<<<(Eint + 255)/256, blk>>>(e_int + Eint, Eint, CNT);
    scatter_k<<<((long)Eint*64 + 255)/256, blk>>>(T, HID, e_int, e_int + Eint, Eint, AGG);
    combine_k<<<combBlocks, blk>>>(AGG, CNT, CR + HID, 2*HID, bl3, H1);

    // ---- out = H3 @ W3 + b3 ----
    dim3 gOut(1, (NCOMM + 127)/128);
    mmagemm<<<gOut, blk>>>(H1, W3T, b3, (float*)d_out, NCOMM, NOUT, HID);
}

// round 13
// speedup vs baseline: 3.1198x; 1.3148x over previous
#include <cuda_runtime.h>
#include <cstdint>

#define NART  50000
#define NCOMM 50000
#define FIN   768
#define PROJ  1024
#define HID   256
#define NOUT  128

// ---------------- scratch (device globals; no allocation allowed) ----------
__device__ __align__(16) float g_Wl12T[2 * PROJ * HID];   // [Wl1^T ; Wl2^T]  [512,1024]
__device__ __align__(16) float g_Wr1T [PROJ * HID];       // Wr1^T [256,1024]
__device__ __align__(16) float g_WaT12[2 * HID * FIN];    // ([W1@Wl1]^T ; [W1@Wl2]^T) [512,768]
__device__ __align__(16) float g_WCR  [2 * HID * FIN];    // ([W2@Wr1]^T ; Wr3^T)      [512,768]
__device__ __align__(16) float g_Wr2T [HID * HID];
__device__ __align__(16) float g_Wl3T [HID * HID];
__device__ __align__(16) float g_W3T  [NOUT * HID];
__device__ __align__(16) float g_ba12 [2 * HID];          // b1@Wl1 | b1@Wl2
__device__ __align__(16) float g_bcr  [2 * HID];          // b2@Wr1 | 0
__device__ __align__(16) float g_A12  [NART * 2 * HID];   // article proj: A1 | A2
__device__ __align__(16) float g_CR   [NCOMM * 2 * HID];  // community proj: C1 | R3
__device__ __align__(16) float g_AGG  [NCOMM * HID];
__device__ __align__(16) float g_CNT  [NCOMM];
__device__ __align__(16) float g_H1   [NCOMM * HID];      // h1, later h3
__device__ __align__(16) float g_H2   [NCOMM * HID];
__device__ __align__(16) float g_T    [NCOMM * HID];

__device__ __forceinline__ float f2tf32rna(float x) {
    uint32_t r;
    asm("cvt.rna.tf32.f32 %0, %1;" : "=r"(r) : "f"(x));
    return __uint_as_float(r);
}
__device__ __forceinline__ float4 tf32x4(float4 v) {
    v.x = f2tf32rna(v.x); v.y = f2tf32rna(v.y);
    v.z = f2tf32rna(v.z); v.w = f2tf32rna(v.w);
    return v;
}

// ---------------- tf32 mma.sync GEMM: C[M,N] = A[M,K] @ BT[N,K]^T (+bias) --
// 128x128 CTA tile, BK=32, 256 threads, warp tile 32x64 (2x8 m16n8k8).
// Static smem, register-prefetch double buffering. Values rna-rounded to tf32
// at smem staging (halves quantization error vs HW truncation).
// Requires N%128==0, K%32==0; M guarded. grid = (N/128, ceil(M/128)).
#define PADK 36

__global__ void __launch_bounds__(256) mmagemm(
    const float* __restrict__ A, const float* __restrict__ BT,
    const float* __restrict__ bias, float* __restrict__ C,
    int M, int N, int K)
{
    __shared__ float As[128][PADK];   // rows are 144B = 9*16B -> float4-aligned
    __shared__ float Bs[128][PADK];
    const int tid  = threadIdx.x;
    const int wid  = tid >> 5, lane = tid & 31;
    const int g    = lane >> 2, t = lane & 3;
    const int bm   = blockIdx.y * 128, bn = blockIdx.x * 128;
    const int wm   = (wid >> 1) * 32, wn = (wid & 1) * 64;

    float acc[2][8][4];
#pragma unroll
    for (int i = 0; i < 2; ++i)
#pragma unroll
        for (int j = 0; j < 8; ++j)
#pragma unroll
            for (int k = 0; k < 4; ++k) acc[i][j][k] = 0.f;

    // per-thread staging coords: 4 float4 segments each for A and B
    int mIdx[4], kqIdx[4];
#pragma unroll
    for (int s = 0; s < 4; ++s) {
        int i = s * 256 + tid;
        mIdx[s]  = i >> 3;          // 0..127
        kqIdx[s] = (i & 7) * 4;     // 0,4,...,28
    }

    const int nCh = K >> 5;
    float4 aReg[4], bReg[4];

    auto fetch = [&](int ci) {
#pragma unroll
        for (int s = 0; s < 4; ++s) {
            const int k0 = ci * 32 + kqIdx[s];
            const int am = bm + mIdx[s];
            aReg[s] = (am < M) ? *(const float4*)(A + (size_t)am * K + k0)
                               : make_float4(0.f, 0.f, 0.f, 0.f);
            bReg[s] = *(const float4*)(BT + (size_t)(bn + mIdx[s]) * K + k0);
        }
    };

    fetch(0);
    for (int ci = 0; ci < nCh; ++ci) {
#pragma unroll
        for (int s = 0; s < 4; ++s) {
            *(float4*)&As[mIdx[s]][kqIdx[s]] = tf32x4(aReg[s]);
            *(float4*)&Bs[mIdx[s]][kqIdx[s]] = tf32x4(bReg[s]);
        }
        __syncthreads();
        if (ci + 1 < nCh) fetch(ci + 1);   // overlap next LDG with MMA

#pragma unroll
        for (int kk = 0; kk < 32; kk += 8) {
            uint32_t aF[2][4], bF[8][2];
#pragma unroll
            for (int tm = 0; tm < 2; ++tm) {
                int r = wm + tm * 16 + g;
                aF[tm][0] = __float_as_uint(As[r][kk + t]);
                aF[tm][1] = __float_as_uint(As[r + 8][kk + t]);
                aF[tm][2] = __float_as_uint(As[r][kk + t + 4]);
                aF[tm][3] = __float_as_uint(As[r + 8][kk + t + 4]);
            }
#pragma unroll
            for (int tn = 0; tn < 8; ++tn) {
                int c = wn + tn * 8 + g;
                bF[tn][0] = __float_as_uint(Bs[c][kk + t]);
                bF[tn][1] = __float_as_uint(Bs[c][kk + t + 4]);
            }
#pragma unroll
            for (int tm = 0; tm < 2; ++tm)
#pragma unroll
                for (int tn = 0; tn < 8; ++tn)
                    asm volatile(
                        "mma.sync.aligned.m16n8k8.row.col.f32.tf32.tf32.f32 "
                        "{%0,%1,%2,%3}, {%4,%5,%6,%7}, {%8,%9}, {%0,%1,%2,%3};"
                        : "+f"(acc[tm][tn][0]), "+f"(acc[tm][tn][1]),
                          "+f"(acc[tm][tn][2]), "+f"(acc[tm][tn][3])
                        : "r"(aF[tm][0]), "r"(aF[tm][1]), "r"(aF[tm][2]), "r"(aF[tm][3]),
                          "r"(bF[tn][0]), "r"(bF[tn][1]));
        }
        __syncthreads();
    }

    // epilogue
#pragma unroll
    for (int tm = 0; tm < 2; ++tm)
#pragma unroll
        for (int half = 0; half < 2; ++half) {
            int row = bm + wm + tm * 16 + g + half * 8;
            if (row >= M) continue;
            float* cr = C + (size_t)row * N + bn + wn;
#pragma unroll
            for (int tn = 0; tn < 8; ++tn) {
                int col = tn * 8 + 2 * t;
                float2 v;
                v.x = acc[tm][tn][half * 2 + 0];
                v.y = acc[tm][tn][half * 2 + 1];
                if (bias) {
                    v.x += bias[bn + wn + col];
                    v.y += bias[bn + wn + col + 1];
                }
                *(float2*)(cr + col) = v;
            }
        }
}

// ---------------- small helpers --------------------------------------------
__global__ void transpose_k(const float* __restrict__ in, float* __restrict__ out,
                            int R, int C)
{
    int t = blockIdx.x * blockDim.x + threadIdx.x;
    if (t >= R * C) return;
    int r = t / C, c = t % C;
    out[(size_t)c * R + r] = in[(size_t)r * C + c];
}

// out[c] = dot(v[0:K], WT[c, 0:K]) — one block per output, coalesced row read
__global__ void __launch_bounds__(256) dotrow_k(
    const float* __restrict__ v, const float* __restrict__ WT,
    float* __restrict__ out, int K)
{
    const int c = blockIdx.x, tid = threadIdx.x;
    const float* row = WT + (size_t)c * K;
    float s = 0.f;
    for (int k = tid; k < K; k += 256) s = fmaf(row[k], v[k], s);
#pragma unroll
    for (int o = 16; o > 0; o >>= 1) s += __shfl_xor_sync(0xFFFFFFFFu, s, o);
    __shared__ float red[8];
    if ((tid & 31) == 0) red[tid >> 5] = s;
    __syncthreads();
    if (tid == 0) {
        float r = red[0];
#pragma unroll
        for (int w = 1; w < 8; ++w) r += red[w];
        out[c] = r;
    }
}

__global__ void count_k(const int* __restrict__ dst, int E, float* __restrict__ cnt)
{
    int e = blockIdx.x * blockDim.x + threadIdx.x;
    if (e < E) atomicAdd(&cnt[dst[e]], 1.0f);
}

// agg[dst,:HID] += feat[src*ld : +HID] — 64 threads/edge, one vector atomic
__global__ void scatter_k(const float* __restrict__ feat, int ld,
                          const int* __restrict__ src, const int* __restrict__ dst,
                          int E, float* __restrict__ agg)
{
    int tt = blockIdx.x * blockDim.x + threadIdx.x;
    int e = tt >> 6;
    if (e >= E) return;
    int c4 = (tt & 63) * 4;
    float4 v = *(const float4*)(feat + (size_t)src[e] * ld + c4);
    float4* o = (float4*)(agg + (size_t)dst[e] * HID + c4);
    atomicAdd(o, v);   // sm_90+: RED.E.ADD.F32.V4
}

// out = relu(agg/max(cnt,1) + bias + other)  (other has leading dim ldO)
__global__ void combine_k(const float* __restrict__ agg, const float* __restrict__ cnt,
                          const float* __restrict__ other, int ldO,
                          const float* __restrict__ bias, float* __restrict__ out)
{
    int t = blockIdx.x * blockDim.x + threadIdx.x;
    if (t >= NCOMM * (HID / 4)) return;
    int i = t >> 6;
    int c4 = (t & 63) * 4;
    float inv = 1.0f / fmaxf(cnt[i], 1.0f);
    float4 a = *(const float4*)(agg + (size_t)i * HID + c4);
    float4 o = *(const float4*)(other + (size_t)i * ldO + c4);
    float4 b = *(const float4*)(bias + c4);
    float4 r;
    r.x = fmaxf(fmaf(a.x, inv, o.x + b.x), 0.f);
    r.y = fmaxf(fmaf(a.y, inv, o.y + b.y), 0.f);
    r.z = fmaxf(fmaf(a.z, inv, o.z + b.z), 0.f);
    r.w = fmaxf(fmaf(a.w, inv, o.w + b.w), 0.f);
    *(float4*)(out + (size_t)i * HID + c4) = r;
}

// ---------------- launch ----------------------------------------------------
extern "C" void kernel_launch(void* const* d_in, const int* in_sizes, int n_in,
                              void* d_out, int out_size)
{
    const float* article_x   = (const float*)d_in[0];
    const float* community_x = (const float*)d_in[1];
    const int*   e_wb  = (const int*)d_in[2];
    const int*   e_mb  = (const int*)d_in[3];
    const int*   e_int = (const int*)d_in[4];
    const float* W1  = (const float*)d_in[5];
    const float* b1  = (const float*)d_in[6];
    const float* W2  = (const float*)d_in[7];
    const float* b2  = (const float*)d_in[8];
    const float* Wl1 = (const float*)d_in[9];
    const float* bl1 = (const float*)d_in[10];
    const float* Wr1 = (const float*)d_in[11];
    const float* Wl2 = (const float*)d_in[12];
    const float* bl2 = (const float*)d_in[13];
    const float* Wr2 = (const float*)d_in[14];
    const float* Wl3 = (const float*)d_in[15];
    const float* bl3 = (const float*)d_in[16];
    const float* Wr3 = (const float*)d_in[17];
    const float* W3  = (const float*)d_in[18];
    const float* b3  = (const float*)d_in[19];

    const int Ewb  = in_sizes[2] / 2;
    const int Emb  = in_sizes[3] / 2;
    const int Eint = in_sizes[4] / 2;

    float *Wl12T,*Wr1T,*WaT12,*WCR,*Wr2T,*Wl3T,*W3T,*ba12,*bcr;
    float *A12,*CR,*AGG,*CNT,*H1,*H2,*T;
    cudaGetSymbolAddress((void**)&Wl12T, g_Wl12T);
    cudaGetSymbolAddress((void**)&Wr1T,  g_Wr1T);
    cudaGetSymbolAddress((void**)&WaT12, g_WaT12);
    cudaGetSymbolAddress((void**)&WCR,   g_WCR);
    cudaGetSymbolAddress((void**)&Wr2T,  g_Wr2T);
    cudaGetSymbolAddress((void**)&Wl3T,  g_Wl3T);
    cudaGetSymbolAddress((void**)&W3T,   g_W3T);
    cudaGetSymbolAddress((void**)&ba12,  g_ba12);
    cudaGetSymbolAddress((void**)&bcr,   g_bcr);
    cudaGetSymbolAddress((void**)&A12,   g_A12);
    cudaGetSymbolAddress((void**)&CR,    g_CR);
    cudaGetSymbolAddress((void**)&AGG,   g_AGG);
    cudaGetSymbolAddress((void**)&CNT,   g_CNT);
    cudaGetSymbolAddress((void**)&H1,    g_H1);
    cudaGetSymbolAddress((void**)&H2,    g_H2);
    cudaGetSymbolAddress((void**)&T,     g_T);

    const dim3 blk(256);

    // ---- weight transposes ----
    transpose_k<<<(PROJ*HID + 255)/256, blk>>>(Wl1, Wl12T, PROJ, HID);
    transpose_k<<<(PROJ*HID + 255)/256, blk>>>(Wl2, Wl12T + PROJ*HID, PROJ, HID);
    transpose_k<<<(PROJ*HID + 255)/256, blk>>>(Wr1, Wr1T, PROJ, HID);
    transpose_k<<<(FIN*HID + 255)/256,  blk>>>(Wr3, WCR + HID*FIN, FIN, HID); // Wr3^T rows 256-511
    transpose_k<<<(HID*HID + 255)/256,  blk>>>(Wr2, Wr2T, HID, HID);
    transpose_k<<<(HID*HID + 255)/256,  blk>>>(Wl3, Wl3T, HID, HID);
    transpose_k<<<(HID*NOUT + 255)/256, blk>>>(W3,  W3T,  HID, NOUT);

    // ---- folded biases: ba = b @ Wl = dot(b, WlT-row) per column ----
    cudaMemsetAsync(bcr, 0, sizeof(float) * 2 * HID);
    dotrow_k<<<HID, blk>>>(b1, Wl12T,            ba12,       PROJ);
    dotrow_k<<<HID, blk>>>(b1, Wl12T + PROJ*HID, ba12 + HID, PROJ);
    dotrow_k<<<HID, blk>>>(b2, Wr1T,             bcr,        PROJ);

    // ---- weight folds (tf32-rna tensor GEMM; W1/W2 row-major are BT form) ----
    dim3 gF1(FIN/128, 4);  // M=512
    dim3 gF2(FIN/128, 2);  // M=256
    mmagemm<<<gF1, blk>>>(Wl12T, W1, nullptr, WaT12, 2*HID, FIN, PROJ);
    mmagemm<<<gF2, blk>>>(Wr1T,  W2, nullptr, WCR,   HID,   FIN, PROJ);

    // ---- node projections (tf32 tensor, rna-rounded), fused N=512 ----
    dim3 gBig(4, (NART + 127)/128);
    mmagemm<<<gBig, blk>>>(article_x,   WaT12, ba12, A12, NART,  2*HID, FIN);
    mmagemm<<<gBig, blk>>>(community_x, WCR,   bcr,  CR,  NCOMM, 2*HID, FIN);

    const int combBlocks = (NCOMM * (HID/4) + 255)/256;
    dim3 gMid(2, (NCOMM + 127)/128);

    // ---- conv1: h1 = relu(segmean_{e_wb}(A1) + bl1 + C1) ----
    cudaMemsetAsync(AGG, 0, sizeof(float) * NCOMM * HID);
    cudaMemsetAsync(CNT, 0, sizeof(float) * NCOMM);
    count_k<<<(Ewb + 255)/256, blk>>>(e_wb + Ewb, Ewb, CNT);
    scatter_k<<<(Ewb*64 + 255)/256, blk>>>(A12, 2*HID, e_wb, e_wb + Ewb, Ewb, AGG);
    combine_k<<<combBlocks, blk>>>(AGG, CNT, CR, 2*HID, bl1, H1);

    // ---- conv2: h2 = relu(segmean_{e_mb}(A2) + bl2 + H1@Wr2) ----
    mmagemm<<<gMid, blk>>>(H1, Wr2T, nullptr, T, NCOMM, HID, HID);
    cudaMemsetAsync(AGG, 0, sizeof(float) * NCOMM * HID);
    cudaMemsetAsync(CNT, 0, sizeof(float) * NCOMM);
    count_k<<<(Emb + 255)/256, blk>>>(e_mb + Emb, Emb, CNT);
    scatter_k<<<(Emb*64 + 255)/256, blk>>>(A12 + HID, 2*HID, e_mb, e_mb + Emb, Emb, AGG);
    combine_k<<<combBlocks, blk>>>(AGG, CNT, T, HID, bl2, H2);

    // ---- conv3: h3 = relu(segmean_{e_int}(H2@Wl3) + bl3 + R3) ----
    mmagemm<<<gMid, blk>>>(H2, Wl3T, nullptr, T, NCOMM, HID, HID);
    cudaMemsetAsync(AGG, 0, sizeof(float) * NCOMM * HID);
    cudaMemsetAsync(CNT, 0, sizeof(float) * NCOMM);
    count_k<<<(Eint + 255)/256, blk>>>(e_int + Eint, Eint, CNT);
    scatter_k<<<((long)Eint*64 + 255)/256, blk>>>(T, HID, e_int, e_int + Eint, Eint, AGG);
    combine_k<<<combBlocks, blk>>>(AGG, CNT, CR + HID, 2*HID, bl3, H1);

    // ---- out = H3 @ W3 + b3 ----
    dim3 gOut(1, (NCOMM + 127)/128);
    mmagemm<<<gOut, blk>>>(H1, W3T, b3, (float*)d_out, NCOMM, NOUT, HID);
}